// round 1
// baseline (speedup 1.0000x reference)
#include <cuda_runtime.h>
#include <cuda_bf16.h>
#include <cstdint>

// TSM: x (B=4, T=16, H=64, W=64, C=256) fp32
// out[..., 0:64]    = x[t+1, ..., 0:64]   (0 at t=T-1)
// out[..., 64:128]  = x[t-1, ..., 64:128] (0 at t=0)
// out[..., 128:256] = x[t, ..., 128:256]
//
// Work in float4 units: C4 = 64 float4 per (b,t,h,w).
// Linear float4 index i:
//   c4  = i & 63
//   bt  = i >> 18      (H*W*C4 = 4096*64 = 262144 = 1<<18)
//   t   = bt & 15      (T = 16)
// shift dt: c4<16 -> +1 ; c4<32 -> -1 ; else 0
// src = i + dt * (1<<18), valid if 0 <= t+dt < 16.

static constexpr int T_LOG2   = 4;       // T = 16
static constexpr int BTSTRIDE = 1 << 18; // float4 per (b,t) slab
static constexpr long long N4 = 16777216LL; // total float4

__global__ __launch_bounds__(256) void tsm_kernel(const float4* __restrict__ in,
                                                  float4* __restrict__ out)
{
    // 4 float4 per thread for MLP; grid sized exactly.
    long long base = (long long)(blockIdx.x) * 1024 + threadIdx.x * 4;

    #pragma unroll
    for (int u = 0; u < 4; ++u) {
        long long i = base + u;
        int c4 = (int)(i & 63);
        int t  = (int)((i >> 18) & ((1 << T_LOG2) - 1));

        int dt = (c4 < 16) ? 1 : ((c4 < 32) ? -1 : 0);
        int ts = t + dt;
        bool valid = (unsigned)ts < 16u;

        float4 v = make_float4(0.f, 0.f, 0.f, 0.f);
        if (valid) {
            v = __ldg(&in[i + (long long)dt * BTSTRIDE]);
        }
        out[i] = v;
    }
}

extern "C" void kernel_launch(void* const* d_in, const int* in_sizes, int n_in,
                              void* d_out, int out_size)
{
    const float4* in = (const float4*)d_in[0];
    float4* out = (float4*)d_out;

    // N4 float4, 4 per thread, 256 threads/block -> N4/1024 blocks
    int blocks = (int)(N4 / 1024); // 16384
    tsm_kernel<<<blocks, 256>>>(in, out);
}

// round 2
// speedup vs baseline: 1.0921x; 1.0921x over previous
#include <cuda_runtime.h>
#include <cuda_bf16.h>
#include <cstdint>

// TSM: x (B=4, T=16, H=64, W=64, C=256) fp32
// out[..., 0:64]    = x[t+1, ..., 0:64]   (0 at t=T-1)
// out[..., 64:128]  = x[t-1, ..., 64:128] (0 at t=0)
// out[..., 128:256] = x[t, ..., 128:256]
//
// float4 units: c4 = i & 63; t = (i >> 18) & 15; slab stride = 1<<18 float4.
// dt = +1 (c4<16), -1 (c4<32), 0 otherwise. Invalid src -> 0.
//
// Coalescing fix vs R1: block-strided unroll (i = blk*1024 + u*256 + tid)
// so every LDG.128/STG.128 has consecutive lanes on consecutive float4
// (4 x 128B lines per warp instruction instead of 16).

static constexpr int BTSTRIDE = 1 << 18;      // float4 per (b,t) slab
static constexpr long long N4 = 16777216LL;   // total float4

__global__ __launch_bounds__(256) void tsm_kernel(const float4* __restrict__ in,
                                                  float4* __restrict__ out)
{
    long long blockBase = (long long)(blockIdx.x) * 1024;
    int tid = threadIdx.x;

    #pragma unroll
    for (int u = 0; u < 4; ++u) {
        long long i = blockBase + u * 256 + tid;
        int c4 = (int)(i & 63);
        int t  = (int)((i >> 18) & 15);

        int dt = (c4 < 16) ? 1 : ((c4 < 32) ? -1 : 0);
        int ts = t + dt;
        bool valid = (unsigned)ts < 16u;

        float4 v = make_float4(0.f, 0.f, 0.f, 0.f);
        if (valid) {
            v = __ldg(&in[i + (long long)dt * BTSTRIDE]);
        }
        out[i] = v;
    }
}

extern "C" void kernel_launch(void* const* d_in, const int* in_sizes, int n_in,
                              void* d_out, int out_size)
{
    const float4* in = (const float4*)d_in[0];
    float4* out = (float4*)d_out;

    int blocks = (int)(N4 / 1024); // 16384
    tsm_kernel<<<blocks, 256>>>(in, out);
}

// round 3
// speedup vs baseline: 1.0960x; 1.0036x over previous
#include <cuda_runtime.h>
#include <cuda_bf16.h>
#include <cstdint>

// TSM: x (B=4, T=16, H=64, W=64, C=256) fp32
// out[..., 0:64)    = x[t+1, ..., 0:64)   (0 at t=T-1)
// out[..., 64:128)  = x[t-1, ..., 64:128) (0 at t=0)
// out[..., 128:256) = x[t, ..., 128:256)
//
// float4 units: c4 = i & 63; t = (i >> 18) & 15; slab stride = 1<<18 float4.
// dt = +1 (c4<16), -1 (c4<32), 0 otherwise. Invalid src -> 0.
//
// R3: block-strided unroll x8 (deeper per-warp LDG batch, fewer inst/byte)
//     + __ldcs/__stcs streaming hints (512MiB single-touch stream vs 126MiB L2).

static constexpr int BTSTRIDE = 1 << 18;      // float4 per (b,t) slab
static constexpr long long N4 = 16777216LL;   // total float4
static constexpr int UNROLL = 8;
static constexpr int TPB = 256;
static constexpr int F4_PER_BLOCK = TPB * UNROLL; // 2048

__global__ __launch_bounds__(TPB) void tsm_kernel(const float4* __restrict__ in,
                                                  float4* __restrict__ out)
{
    long long blockBase = (long long)(blockIdx.x) * F4_PER_BLOCK;
    int tid = threadIdx.x;

    float4 v[UNROLL];

    #pragma unroll
    for (int u = 0; u < UNROLL; ++u) {
        long long i = blockBase + u * TPB + tid;
        int c4 = (int)(i & 63);
        int t  = (int)((i >> 18) & 15);

        int dt = (c4 < 16) ? 1 : ((c4 < 32) ? -1 : 0);
        int ts = t + dt;
        bool valid = (unsigned)ts < 16u;

        v[u] = make_float4(0.f, 0.f, 0.f, 0.f);
        if (valid) {
            v[u] = __ldcs(&in[i + (long long)dt * BTSTRIDE]);
        }
    }

    #pragma unroll
    for (int u = 0; u < UNROLL; ++u) {
        long long i = blockBase + u * TPB + tid;
        __stcs(&out[i], v[u]);
    }
}

extern "C" void kernel_launch(void* const* d_in, const int* in_sizes, int n_in,
                              void* d_out, int out_size)
{
    const float4* in = (const float4*)d_in[0];
    float4* out = (float4*)d_out;

    int blocks = (int)(N4 / F4_PER_BLOCK); // 8192
    tsm_kernel<<<blocks, TPB>>>(in, out);
}